// round 10
// baseline (speedup 1.0000x reference)
#include <cuda_runtime.h>
#include <cuda_bf16.h>

// ---------------- problem constants ----------------
#define B_   2
#define L_   2048
#define D_   512
#define P_   32
#define M_   1024
#define H_   8
#define HD_  64
#define WIN_ 256
#define S_   (P_ + L_)     // 2080
#define R_   (B_ * S_)     // 4160
#define EPS_ 1e-5f

#define RD2  (R_ * D_ / 2)     // words in a bf16 [R,D] buffer
#define RM2  (R_ * M_ / 2)
#define STW  (B_ * M_ * D_ / 2)
#define WK2  (D_ * 512 / 2)
#define MK2  (M_ * D_ / 2)

// ---------------- fp32 scratch (only where fp32 is still consumed) -------
__device__ float g_w[R_ * M_];          // gating out -> softmax reads
__device__ float g_w2[R_ * M_];
__device__ float g_memout[R_ * D_];     // -> LN1
__device__ float g_qh[R_ * D_];         // -> attention
__device__ float g_kh[R_ * D_];
__device__ float g_vh[R_ * D_];
__device__ float g_ao2[R_ * D_];        // -> LN2

// ---------------- bf16 hi/lo operand buffers (as 32-bit words) -----------
__device__ unsigned cb_h[RD2], cb_l[RD2];        // combined
__device__ unsigned k_h[RD2],  k_l[RD2];
__device__ unsigned q_h[RD2],  q_l[RD2];
__device__ unsigned v_h[RD2],  v_l[RD2];
__device__ unsigned w_h[RM2],  w_l[RM2];         // softmax(w_write)
__device__ unsigned u_h[RM2],  u_l[RM2];         // softmax(w_read)
__device__ unsigned st_h[STW], st_l[STW];        // state
__device__ unsigned hh_h[RD2], hh_l[RD2];        // LN1 out
__device__ unsigned ao_h[RD2], ao_l[RD2];        // attention out
__device__ unsigned g2_h[RD2], g2_l[RD2];        // LN2 out
// converted weights
__device__ unsigned mk_h[MK2],  mk_l[MK2];
__device__ unsigned wk_h[WK2],  wk_l[WK2];
__device__ unsigned wv_h[WK2],  wv_l[WK2];
__device__ unsigned wq_h[WK2],  wq_l[WK2];
__device__ unsigned aq_h[WK2],  aq_l[WK2];
__device__ unsigned ak_h[WK2],  ak_l[WK2];
__device__ unsigned av_h[WK2],  av_l[WK2];
__device__ unsigned aw_h[WK2],  aw_l[WK2];
__device__ unsigned ow_h[WK2],  ow_l[WK2];

// ---------------- bf16 m16n8k16 MMA ----------------
#define MMA_BF16(d, a0, a1, a2, a3, b0, b1) \
    asm("mma.sync.aligned.m16n8k16.row.col.f32.bf16.bf16.f32 " \
        "{%0,%1,%2,%3}, {%4,%5,%6,%7}, {%8,%9}, {%0,%1,%2,%3};" \
        : "+f"((d)[0]), "+f"((d)[1]), "+f"((d)[2]), "+f"((d)[3]) \
        : "r"(a0), "r"(a1), "r"(a2), "r"(a3), "r"(b0), "r"(b1))

// hi/lo bf16 split of a float pair; packed words have LOW half = first elem.
__device__ __forceinline__ void hilo2(float x, float y, unsigned& h, unsigned& l) {
    __nv_bfloat162 hb = __floats2bfloat162_rn(x, y);
    float2 hf = __bfloat1622float2(hb);
    __nv_bfloat162 lb = __floats2bfloat162_rn(x - hf.x, y - hf.y);
    h = reinterpret_cast<unsigned&>(hb);
    l = reinterpret_cast<unsigned&>(lb);
}

// smem tile: [16 kpairs][136 cols] uints per matrix-half (R8 layout).
#define KPS  16
#define TSTR 136
#define MHALF (KPS * TSTR)
#define BUFW  (4 * MHALF)
#define BF_SMEM_BYTES (2 * BUFW * 4)

// stage from bf16 word source [rows][ldw words] (k fast; words = {k,k+1})
__device__ __forceinline__ void stage_rm16(
    const unsigned* __restrict__ Hs, const unsigned* __restrict__ Ls,
    int r0, int RM, int ldw, int kw0,
    unsigned* __restrict__ Hi, unsigned* __restrict__ Lo, int tid) {
    const int row = tid >> 1;
    const int kq  = (tid & 1) << 3;       // kp word offset 0 / 8
    const bool ok = (r0 + row) < RM;
    uint4 h0, h1, l0, l1;
    if (ok) {
        const unsigned* ph = Hs + (long)(r0 + row) * ldw + kw0 + kq;
        const unsigned* pl = Ls + (long)(r0 + row) * ldw + kw0 + kq;
        h0 = *(const uint4*)(ph); h1 = *(const uint4*)(ph + 4);
        l0 = *(const uint4*)(pl); l1 = *(const uint4*)(pl + 4);
    } else {
        h0 = h1 = l0 = l1 = make_uint4(0u, 0u, 0u, 0u);
    }
    unsigned hw[8] = {h0.x, h0.y, h0.z, h0.w, h1.x, h1.y, h1.z, h1.w};
    unsigned lw[8] = {l0.x, l0.y, l0.z, l0.w, l1.x, l1.y, l1.z, l1.w};
#pragma unroll
    for (int i = 0; i < 8; i++) {
        Hi[(kq + i) * TSTR + row] = hw[i];
        Lo[(kq + i) * TSTR + row] = lw[i];
    }
}

// stage from bf16 word source [K][ldw words] (cols fast) -> interleave 2 k-rows
__device__ __forceinline__ void stage_tr16(
    const unsigned* __restrict__ Hs, const unsigned* __restrict__ Ls,
    int c0, int CM, int ldw, int k0,
    unsigned* __restrict__ Hi, unsigned* __restrict__ Lo, int tid) {
    const int kp = tid >> 4;
    const int cq = (tid & 15) << 3;       // col offset (elems)
    const bool ok = (c0 + cq) < CM;
    const long o0 = (long)(k0 + 2 * kp) * ldw + ((c0 + cq) >> 1);
    uint4 xh, yh, xl, yl;
    if (ok) {
        xh = *(const uint4*)(Hs + o0); yh = *(const uint4*)(Hs + o0 + ldw);
        xl = *(const uint4*)(Ls + o0); yl = *(const uint4*)(Ls + o0 + ldw);
    } else {
        xh = yh = xl = yl = make_uint4(0u, 0u, 0u, 0u);
    }
    unsigned oh[8], ol[8];
    const unsigned* xw = &xh.x; const unsigned* yw = &yh.x;
#pragma unroll
    for (int m = 0; m < 4; m++) {
        oh[2 * m]     = __byte_perm(xw[m], yw[m], 0x5410);
        oh[2 * m + 1] = __byte_perm(xw[m], yw[m], 0x7632);
    }
    xw = &xl.x; yw = &yl.x;
#pragma unroll
    for (int m = 0; m < 4; m++) {
        ol[2 * m]     = __byte_perm(xw[m], yw[m], 0x5410);
        ol[2 * m + 1] = __byte_perm(xw[m], yw[m], 0x7632);
    }
    *(uint4*)&Hi[kp * TSTR + cq]     = make_uint4(oh[0], oh[1], oh[2], oh[3]);
    *(uint4*)&Hi[kp * TSTR + cq + 4] = make_uint4(oh[4], oh[5], oh[6], oh[7]);
    *(uint4*)&Lo[kp * TSTR + cq]     = make_uint4(ol[0], ol[1], ol[2], ol[3]);
    *(uint4*)&Lo[kp * TSTR + cq + 4] = make_uint4(ol[4], ol[5], ol[6], ol[7]);
}

// ---------------- bf16 2-split GEMM core: 128x128 tile, K-slab 32 --------
// ATR=0: A bf16 [M,K] (k fast).  ATR=1: A bf16 [K,M].
// BTR=0: B bf16 [K,N] (n fast).  BTR=1: B bf16 [N,K] (k fast).
// O16=0: write C fp32 (+bias).  O16=1: write bf16 hi/lo pair.
template<int ATR, int BTR, int O16>
__device__ __forceinline__ void bf_core(
    const unsigned* __restrict__ Ah, const unsigned* __restrict__ Al,
    const unsigned* __restrict__ Bh, const unsigned* __restrict__ Bl,
    float* __restrict__ C, unsigned* __restrict__ Ch, unsigned* __restrict__ Cl,
    int M, int N, int K, const float* __restrict__ bias) {
    extern __shared__ unsigned smg[];
    const int tid = threadIdx.x, lane = tid & 31, wid = tid >> 5;
    const int wm = (wid >> 2) * 64, wn = (wid & 3) * 32;
    const int m0 = blockIdx.y * 128, n0 = blockIdx.x * 128;
    const int ldaw = (ATR == 0) ? (K >> 1) : (M >> 1);
    const int ldbw = (BTR == 0) ? (N >> 1) : (K >> 1);

    float acc[4][4][4];
#pragma unroll
    for (int i = 0; i < 4; i++)
#pragma unroll
        for (int j = 0; j < 4; j++)
#pragma unroll
            for (int c = 0; c < 4; c++) acc[i][j][c] = 0.f;

    auto stage = [&](int s, int b) {
        const int k0 = s * 32;
        unsigned* AH = smg + b * BUFW;
        unsigned* AL = AH + MHALF;
        unsigned* BH = AH + 2 * MHALF;
        unsigned* BL = AH + 3 * MHALF;
        if (ATR == 0) stage_rm16(Ah, Al, m0, M, ldaw, k0 >> 1, AH, AL, tid);
        else          stage_tr16(Ah, Al, m0, M, ldaw, k0, AH, AL, tid);
        if (BTR == 0) stage_tr16(Bh, Bl, n0, N, ldbw, k0, BH, BL, tid);
        else          stage_rm16(Bh, Bl, n0, N, ldbw, k0 >> 1, BH, BL, tid);
    };

    const int slabs = K >> 5;
    stage(0, 0);
    __syncthreads();

    for (int s = 0; s < slabs; s++) {
        const int buf = s & 1;
        const unsigned* AH = smg + buf * BUFW;
        const unsigned* AL = AH + MHALF;
        const unsigned* BH = AH + 2 * MHALF;
        const unsigned* BL = AH + 3 * MHALF;
#pragma unroll
        for (int t = 0; t < 2; t++) {
            const int kb = (t * 8 + (lane & 3)) * TSTR;
            const int k4 = kb + 4 * TSTR;
            const int rsel = lane >> 2;
            unsigned bh0[4], bh1[4], bl0[4], bl1[4];
#pragma unroll
            for (int j = 0; j < 4; j++) {
                int c = wn + j * 8 + rsel;
                bh0[j] = BH[kb + c]; bh1[j] = BH[k4 + c];
                bl0[j] = BL[kb + c]; bl1[j] = BL[k4 + c];
            }
#pragma unroll
            for (int i = 0; i < 4; i++) {
                int c = wm + i * 16 + rsel;
                unsigned h0 = AH[kb + c], h1 = AH[kb + c + 8];
                unsigned h2 = AH[k4 + c], h3 = AH[k4 + c + 8];
                unsigned l0 = AL[kb + c], l1 = AL[kb + c + 8];
                unsigned l2 = AL[k4 + c], l3 = AL[k4 + c + 8];
#pragma unroll
                for (int j = 0; j < 4; j++) {
                    MMA_BF16(acc[i][j], h0, h1, h2, h3, bh0[j], bh1[j]);
                    MMA_BF16(acc[i][j], h0, h1, h2, h3, bl0[j], bl1[j]);
                    MMA_BF16(acc[i][j], l0, l1, l2, l3, bh0[j], bh1[j]);
                }
            }
        }
        if (s + 1 < slabs) stage(s + 1, buf ^ 1);
        __syncthreads();
    }

    const int er = lane >> 2, ec = (lane & 3) * 2;
#pragma unroll
    for (int i = 0; i < 4; i++) {
#pragma unroll
        for (int j = 0; j < 4; j++) {
            const int cc = n0 + wn + j * 8 + ec;
            const int r0w = m0 + wm + i * 16 + er;
            const int r1w = r0w + 8;
            if (O16) {
                unsigned h0, l0, h1, l1;
                hilo2(acc[i][j][0], acc[i][j][1], h0, l0);
                hilo2(acc[i][j][2], acc[i][j][3], h1, l1);
                if (r0w < M) {
                    long wo = (long)r0w * (N >> 1) + (cc >> 1);
                    Ch[wo] = h0; Cl[wo] = l0;
                }
                if (r1w < M) {
                    long wo = (long)r1w * (N >> 1) + (cc >> 1);
                    Ch[wo] = h1; Cl[wo] = l1;
                }
            } else {
                float b0 = 0.f, b1 = 0.f;
                if (bias) { b0 = bias[cc]; b1 = bias[cc + 1]; }
                if (r0w < M)
                    *(float2*)(C + (long)r0w * N + cc) =
                        make_float2(acc[i][j][0] + b0, acc[i][j][1] + b1);
                if (r1w < M)
                    *(float2*)(C + (long)r1w * N + cc) =
                        make_float2(acc[i][j][2] + b0, acc[i][j][3] + b1);
            }
        }
    }
}

template<int ATR, int BTR, int O16>
__global__ void __launch_bounds__(256, 2)
bf_gemm(const unsigned* __restrict__ Ah, const unsigned* __restrict__ Al, long sAw,
        const unsigned* __restrict__ Bh, const unsigned* __restrict__ Bl, long sBw,
        float* __restrict__ C, long sC,
        unsigned* __restrict__ Ch, unsigned* __restrict__ Cl, long sCw,
        int M, int N, int K, const float* __restrict__ bias) {
    const long z = blockIdx.z;
    bf_core<ATR, BTR, O16>(Ah + z * sAw, Al + z * sAw, Bh + z * sBw, Bl + z * sBw,
                           C ? C + z * sC : nullptr,
                           Ch ? Ch + z * sCw : nullptr,
                           Cl ? Cl + z * sCw : nullptr, M, N, K, bias);
}

// 3 GEMMs sharing A (bf16), distinct B / outputs.
struct PB3 {
    const unsigned *bh0, *bl0, *bh1, *bl1, *bh2, *bl2;
    unsigned *ch0, *cl0, *ch1, *cl1, *ch2, *cl2;
};
__global__ void __launch_bounds__(256, 2)
bf_gemm3(const unsigned* __restrict__ Ah, const unsigned* __restrict__ Al,
         PB3 p, int M, int N, int K, int out16,
         float* c0f, float* c1f, float* c2f) {
    const int z = blockIdx.z;
    const unsigned* Bh = (z == 0) ? p.bh0 : (z == 1) ? p.bh1 : p.bh2;
    const unsigned* Bl = (z == 0) ? p.bl0 : (z == 1) ? p.bl1 : p.bl2;
    if (out16) {
        unsigned* Ch = (z == 0) ? p.ch0 : (z == 1) ? p.ch1 : p.ch2;
        unsigned* Cl = (z == 0) ? p.cl0 : (z == 1) ? p.cl1 : p.cl2;
        bf_core<0, 0, 1>(Ah, Al, Bh, Bl, nullptr, Ch, Cl, M, N, K, nullptr);
    } else {
        float* C = (z == 0) ? c0f : (z == 1) ? c1f : c2f;
        bf_core<0, 0, 0>(Ah, Al, Bh, Bl, C, nullptr, nullptr, M, N, K, nullptr);
    }
}

// 2 GEMMs sharing B = mem_keys (bf16 [N,K]), distinct A, fp32 out.
struct PA2 { const unsigned *ah0, *al0, *ah1, *al1; float *c0, *c1; };
__global__ void __launch_bounds__(256, 2)
bf_gemm2(PA2 p, const unsigned* __restrict__ Bh, const unsigned* __restrict__ Bl,
         int M, int N, int K) {
    const int z = blockIdx.z;
    bf_core<0, 1, 0>(z ? p.ah1 : p.ah0, z ? p.al1 : p.al0, Bh, Bl,
                     z ? p.c1 : p.c0, nullptr, nullptr, M, N, K, nullptr);
}

// ---------------- concat -> bf16 hi/lo ----------------
__global__ void concat16(const float* __restrict__ x, const float* __restrict__ pm,
                         unsigned* __restrict__ ch, unsigned* __restrict__ cl) {
    long e = ((long)blockIdx.x * 256 + threadIdx.x) * 4;
    if (e >= (long)R_ * D_) return;
    int d = (int)(e % D_);
    long sd = e / D_;
    int s = (int)(sd % S_);
    int b = (int)(sd / S_);
    float4 f = (s < P_) ? *(const float4*)(pm + s * D_ + d)
                        : *(const float4*)(x + ((long)b * L_ + (s - P_)) * D_ + d);
    unsigned h0, l0, h1, l1;
    hilo2(f.x, f.y, h0, l0);
    hilo2(f.z, f.w, h1, l1);
    *(uint2*)&ch[e >> 1] = make_uint2(h0, h1);
    *(uint2*)&cl[e >> 1] = make_uint2(l0, l1);
}

// ---------------- weight conversion (9 tensors, batched via grid.z) -------
struct Conv9 {
    const float* s[9];
    unsigned* h[9];
    unsigned* l[9];
    int nw[9];   // words
};
__global__ void conv_weights(Conv9 c) {
    int z = blockIdx.z;
    long t = (long)blockIdx.x * 256 + threadIdx.x;   // thread = 2 words = 4 floats
    if (2 * t >= c.nw[z]) return;
    float4 f = *(const float4*)(c.s[z] + 4 * t);
    unsigned h0, l0, h1, l1;
    hilo2(f.x, f.y, h0, l0);
    hilo2(f.z, f.w, h1, l1);
    *(uint2*)&c.h[z][2 * t] = make_uint2(h0, h1);
    *(uint2*)&c.l[z][2 * t] = make_uint2(l0, l1);
}

// ---------------- row softmax over 1024 cols -> bf16 hi/lo ----------------
__global__ void __launch_bounds__(256)
softmax16(const float* __restrict__ w,
          unsigned* __restrict__ oh, unsigned* __restrict__ ol) {
    __shared__ float sh[8];
    const float* row = w + (long)blockIdx.x * M_;
    const int tid = threadIdx.x;
    float4 v = *(const float4*)(row + tid * 4);
    float mx = fmaxf(fmaxf(v.x, v.y), fmaxf(v.z, v.w));
#pragma unroll
    for (int o = 16; o; o >>= 1) mx = fmaxf(mx, __shfl_xor_sync(~0u, mx, o));
    if ((tid & 31) == 0) sh[tid >> 5] = mx;
    __syncthreads();
    mx = sh[0];
#pragma unroll
    for (int i = 1; i < 8; i++) mx = fmaxf(mx, sh[i]);
    v.x = __expf(v.x - mx); v.y = __expf(v.y - mx);
    v.z = __expf(v.z - mx); v.w = __expf(v.w - mx);
    float s = v.x + v.y + v.z + v.w;
#pragma unroll
    for (int o = 16; o; o >>= 1) s += __shfl_xor_sync(~0u, s, o);
    __syncthreads();
    if ((tid & 31) == 0) sh[tid >> 5] = s;
    __syncthreads();
    s = sh[0] + sh[1] + sh[2] + sh[3] + sh[4] + sh[5] + sh[6] + sh[7];
    float inv = 1.f / s;
    v.x *= inv; v.y *= inv; v.z *= inv; v.w *= inv;
    unsigned h0, l0, h1, l1;
    hilo2(v.x, v.y, h0, l0);
    hilo2(v.z, v.w, h1, l1);
    long wo = (long)blockIdx.x * (M_ / 2) + tid * 2;
    *(uint2*)&oh[wo] = make_uint2(h0, h1);
    *(uint2*)&ol[wo] = make_uint2(l0, l1);
}

// ---------------- layernorm (512) -> bf16 hi/lo ----------------
__global__ void __launch_bounds__(128)
layernorm16(const float* __restrict__ in,
            unsigned* __restrict__ oh, unsigned* __restrict__ ol,
            const float* __restrict__ gw, const float* __restrict__ bw) {
    __shared__ float sh[4];
    const int tid = threadIdx.x;
    const float* row = in + (long)blockIdx.x * D_;
    float4 v = *(const float4*)(row + tid * 4);
    float s = v.x + v.y + v.z + v.w;
#pragma unroll
    for (int o = 16; o; o >>= 1) s += __shfl_xor_sync(~0u, s, o);
    if ((tid & 31) == 0) sh[tid >> 5] = s;
    __syncthreads();
    float mu = (sh[0] + sh[1] + sh[2] + sh[3]) * (1.f / 512.f);
    float dx = v.x - mu, dy = v.y - mu, dz = v.z - mu, dw = v.w - mu;
    float sq = dx * dx + dy * dy + dz * dz + dw * dw;
#pragma unroll
    for (int o = 16; o; o >>= 1) sq += __shfl_xor_sync(~0u, sq, o);
    __syncthreads();
    if ((tid & 31) == 0) sh[tid >> 5] = sq;
    __syncthreads();
    float var = (sh[0] + sh[1] + sh[2] + sh[3]) * (1.f / 512.f);
    float inv = rsqrtf(var + EPS_);
    float4 g4 = *(const float4*)(gw + tid * 4);
    float4 b4 = *(const float4*)(bw + tid * 4);
    float ox = dx * inv * g4.x + b4.x;
    float oy = dy * inv * g4.y + b4.y;
    float oz = dz * inv * g4.z + b4.z;
    float ow = dw * inv * g4.w + b4.w;
    unsigned h0, l0, h1, l1;
    hilo2(ox, oy, h0, l0);
    hilo2(oz, ow, h1, l1);
    long wo = (long)blockIdx.x * (D_ / 2) + tid * 2;
    *(uint2*)&oh[wo] = make_uint2(h0, h1);
    *(uint2*)&ol[wo] = make_uint2(l0, l1);
}

// ---------------- banded flash attention (R6 core, bf16 hi/lo output) -----
#define QS_STR 68
#define PS_STR 69
#define ATTN_SMEM_FLOATS (64 * QS_STR + 64 * PS_STR + 64 * 64 * 2)
__global__ void __launch_bounds__(256)
attn_kernel(const float* __restrict__ qh, const float* __restrict__ kh,
            const float* __restrict__ vh,
            unsigned* __restrict__ AOh, unsigned* __restrict__ AOl) {
    extern __shared__ float smema[];
    float* Qs = smema;
    float* Ps = smema + 64 * QS_STR;
    float* Ks = Ps + 64 * PS_STR;
    float* Vs = Ks + 64 * 64;

    const int qt = blockIdx.x, h = blockIdx.y, b = blockIdx.z;
    const int q0 = qt * 64;
    const int tid = threadIdx.x;
    const int r = tid >> 2, cg = tid & 3;
    const int rowb = cg * 16;
    const long base = (long)b * S_ * D_ + h * HD_;

    for (int i = tid; i < 64 * 16; i += 256) {
        int rr = i >> 4, c4 = (i & 15) * 4;
        float4 qv = make_float4(0.f, 0.f, 0.f, 0.f);
        if (q0 + rr < S_)
            qv = *(const float4*)(qh + base + (long)(q0 + rr) * D_ + c4);
        *(float4*)&Qs[rr * QS_STR + c4] = qv;
    }

    float m = -1e30f, l = 0.f;
    float o[16];
#pragma unroll
    for (int i = 0; i < 16; i++) o[i] = 0.f;

    int klo = q0 - (WIN_ - 1); if (klo < 0) klo = 0;
    int khi = q0 + 63 + WIN_ - 1; if (khi > S_ - 1) khi = S_ - 1;

    for (int kt = klo >> 6; kt <= khi >> 6; ++kt) {
        const int k0 = kt << 6;
        __syncthreads();
        for (int i = tid; i < 64 * 16; i += 256) {
            int rr = i >> 4, c4 = (i & 15) * 4;
            float4 kv = make_float4(0.f, 0.f, 0.f, 0.f), vv = kv;
            if (k0 + rr < S_) {
                long g = base + (long)(k0 + rr) * D_ + c4;
                kv = *(const float4*)(kh + g);
                vv = *(const float4*)(vh + g);
            }
            *(float4*)&Ks[rr * 64 + (c4 ^ ((rr >> 4) * 8))] = kv;
            *(float4*)&Vs[rr * 64 + (c4 ^ ((c4 >> 5) * 8))] = vv;
        }
        __syncthreads();

        float sreg[16];
#pragma unroll
        for (int j = 0; j < 16; j++) sreg[j] = 0.f;
        const int kx = cg * 8;
#pragma unroll 4
        for (int d0 = 0; d0 < 64; d0 += 4) {
            float4 q4 = *(const float4*)&Qs[r * QS_STR + d0];
            const int kc = d0 ^ kx;
#pragma unroll
            for (int j = 0; j < 16; j++) {
                float4 k4 = *(const float4*)&Ks[(rowb + j) * 64 + kc];
                sreg[j] += q4.x * k4.x + q4.y * k4.y + q4.z * k4.z + q4.w * k4.w;
            }
        }

        const int qi = q0 + r;
        float tmax = -1e30f;
#pragma unroll
        for (int j = 0; j < 16; j++) {
            int kj = k0 + rowb + j;
            int diff = qi - kj; if (diff < 0) diff = -diff;
            bool valid = (kj < S_) && (diff < WIN_);
            sreg[j] = valid ? sreg[j] * 0.125f : -1e30f;
            tmax = fmaxf(tmax, sreg[j]);
        }
        tmax = fmaxf(tmax, __shfl_xor_sync(0xffffffffu, tmax, 1));
        tmax = fmaxf(tmax, __shfl_xor_sync(0xffffffffu, tmax, 2));
        float mnew = fmaxf(m, tmax);
        float alpha = __expf(m - mnew);
        float lsum = 0.f;
#pragma unroll
        for (int j = 0; j < 16; j++) {
            float p = (sreg[j] > -0.9e30f) ? __expf(sreg[j] - mnew) : 0.f;
            Ps[r * PS_STR + rowb + j] = p;
            lsum += p;
        }
        lsum += __shfl_xor_sync(0xffffffffu, lsum, 1);
        lsum += __shfl_xor_sync(0xffffffffu, lsum, 2);
        l = l * alpha + lsum;
        m = mnew;
#pragma unroll
        for (int i = 0; i < 16; i++) o[i] *= alpha;
        __syncthreads();

        const int vx = (cg >> 1) * 8;
#pragma unroll 4
        for (int j = 0; j < 64; j++) {
            float p = Ps[r * PS_STR + j];
#pragma unroll
            for (int i4 = 0; i4 < 4; i4++) {
                float4 v4 = *(const float4*)&Vs[j * 64 + ((rowb + i4 * 4) ^ vx)];
                o[i4 * 4 + 0] += p * v4.x;
                o[i4 * 4 + 1] += p * v4.y;
                o[i4 * 4 + 2] += p * v4.z;
                o[i4 * 4 + 3] += p * v4.w;
            }
        }
    }

    const int qi = q0 + r;
    if (qi < S_) {
        float inv = 1.f / l;
        unsigned hw[8], lw[8];
#pragma unroll
        for (int i2 = 0; i2 < 8; i2++)
            hilo2(o[2 * i2] * inv, o[2 * i2 + 1] * inv, hw[i2], lw[i2]);
        long wo = (base + (long)qi * D_ + rowb) >> 1;
        *(uint4*)&AOh[wo]     = make_uint4(hw[0], hw[1], hw[2], hw[3]);
        *(uint4*)&AOh[wo + 4] = make_uint4(hw[4], hw[5], hw[6], hw[7]);
        *(uint4*)&AOl[wo]     = make_uint4(lw[0], lw[1], lw[2], lw[3]);
        *(uint4*)&AOl[wo + 4] = make_uint4(lw[4], lw[5], lw[6], lw[7]);
    }
}

// ---------------- launch ----------------
extern "C" void kernel_launch(void* const* d_in, const int* in_sizes, int n_in,
                              void* d_out, int out_size) {
    const float* x        = (const float*)d_in[0];
    const float* pm       = (const float*)d_in[1];
    const float* mem_keys = (const float*)d_in[2];
    const float* mem_Wk   = (const float*)d_in[3];
    const float* mem_Wv   = (const float*)d_in[4];
    const float* mem_Wq   = (const float*)d_in[5];
    const float* attn_Wq  = (const float*)d_in[6];
    const float* attn_Wk  = (const float*)d_in[7];
    const float* attn_Wv  = (const float*)d_in[8];
    const float* attn_Wo  = (const float*)d_in[9];
    const float* ln1_g    = (const float*)d_in[10];
    const float* ln1_b    = (const float*)d_in[11];
    const float* ln2_g    = (const float*)d_in[12];
    const float* ln2_b    = (const float*)d_in[13];
    const float* out_W    = (const float*)d_in[14];
    const float* out_b    = (const float*)d_in[15];
    float* out = (float*)d_out;

    float *w, *w2, *memout, *qh, *kh, *vh, *ao2;
    cudaGetSymbolAddress((void**)&w, g_w);
    cudaGetSymbolAddress((void**)&w2, g_w2);
    cudaGetSymbolAddress((void**)&memout, g_memout);
    cudaGetSymbolAddress((void**)&qh, g_qh);
    cudaGetSymbolAddress((void**)&kh, g_kh);
    cudaGetSymbolAddress((void**)&vh, g_vh);
    cudaGetSymbolAddress((void**)&ao2, g_ao2);

#define GETU(name, sym) unsigned* name; cudaGetSymbolAddress((void**)&name, sym)
    GETU(cbh, cb_h); GETU(cbl, cb_l);
    GETU(kh2, k_h);  GETU(kl2, k_l);
    GETU(qh2, q_h);  GETU(ql2, q_l);
    GETU(vh2, v_h);  GETU(vl2, v_l);
    GETU(wh2, w_h);  GETU(wl2, w_l);
    GETU(uh2, u_h);  GETU(ul2, u_l);
    GETU(sth, st_h); GETU(stl, st_l);
    GETU(hhh, hh_h); GETU(hhl, hh_l);
    GETU(aoh, ao_h); GETU(aol, ao_l);
    GETU(g2h, g2_h); GETU(g2l, g2_l);
    GETU(mkh, mk_h); GETU(mkl, mk_l);
    GETU(wkh, wk_h); GETU(wkl, wk_l);
    GETU(wvh, wv_h); GETU(wvl, wv_l);
    GETU(wqh, wq_h); GETU(wql, wq_l);
    GETU(aqh, aq_h); GETU(aql, aq_l);
    GETU(akh, ak_h); GETU(akl, ak_l);
    GETU(avh, av_h); GETU(avl, av_l);
    GETU(awh, aw_h); GETU(awl, aw_l);
    GETU(owh, ow_h); GETU(owl, ow_l);
#undef GETU

    cudaFuncSetAttribute(attn_kernel,
                         cudaFuncAttributeMaxDynamicSharedMemorySize,
                         ATTN_SMEM_FLOATS * (int)sizeof(float));
    cudaFuncSetAttribute(bf_gemm3,
                         cudaFuncAttributeMaxDynamicSharedMemorySize, BF_SMEM_BYTES);
    cudaFuncSetAttribute(bf_gemm2,
                         cudaFuncAttributeMaxDynamicSharedMemorySize, BF_SMEM_BYTES);
    cudaFuncSetAttribute(bf_gemm<1, 0, 1>,
                         cudaFuncAttributeMaxDynamicSharedMemorySize, BF_SMEM_BYTES);
    cudaFuncSetAttribute(bf_gemm<0, 0, 0>,
                         cudaFuncAttributeMaxDynamicSharedMemorySize, BF_SMEM_BYTES);

    // 0. convert weights + mem_keys to bf16 hi/lo (once per call)
    {
        Conv9 c;
        c.s[0] = mem_keys; c.h[0] = mkh; c.l[0] = mkl; c.nw[0] = MK2;
        c.s[1] = mem_Wk;  c.h[1] = wkh; c.l[1] = wkl; c.nw[1] = WK2;
        c.s[2] = mem_Wv;  c.h[2] = wvh; c.l[2] = wvl; c.nw[2] = WK2;
        c.s[3] = mem_Wq;  c.h[3] = wqh; c.l[3] = wql; c.nw[3] = WK2;
        c.s[4] = attn_Wq; c.h[4] = aqh; c.l[4] = aql; c.nw[4] = WK2;
        c.s[5] = attn_Wk; c.h[5] = akh; c.l[5] = akl; c.nw[5] = WK2;
        c.s[6] = attn_Wv; c.h[6] = avh; c.l[6] = avl; c.nw[6] = WK2;
        c.s[7] = attn_Wo; c.h[7] = awh; c.l[7] = awl; c.nw[7] = WK2;
        c.s[8] = out_W;   c.h[8] = owh; c.l[8] = owl; c.nw[8] = WK2;
        conv_weights<<<dim3(MK2 / 512, 1, 9), 256>>>(c);
    }

    // 1. combined -> bf16
    concat16<<<(R_ * D_ / 4 + 255) / 256, 256>>>(x, pm, cbh, cbl);

    const int MT = (R_ + 127) / 128;   // 33

    // 2. memory k/v/q projections -> bf16 outputs
    {
        PB3 p{wkh, wkl, wvh, wvl, wqh, wql,
              kh2, kl2, vh2, vl2, qh2, ql2};
        bf_gemm3<<<dim3(4, MT, 3), 256, BF_SMEM_BYTES>>>(
            cbh, cbl, p, R_, D_, D_, 1, nullptr, nullptr, nullptr);
    }

    // 3. gating: w_write = k@mkT, w_read = q@mkT -> fp32 for softmax
    {
        PA2 p{kh2, kl2, qh2, ql2, w, w2};
        bf_gemm2<<<dim3(8, MT, 2), 256, BF_SMEM_BYTES>>>(p, mkh, mkl, R_, M_, D_);
    }
    softmax16<<<R_, 256>>>(w, wh2, wl2);
    softmax16<<<R_, 256>>>(w2, uh2, ul2);

    // 4. state[b] = w_write[b]^T @ v[b]  (A bf16 [S,M] used transposed; B bf16 [S,D])
    bf_gemm<1, 0, 1><<<dim3(4, 8, B_), 256, BF_SMEM_BYTES>>>(
        wh2, wl2, (long)S_ * M_ / 2,
        vh2, vl2, (long)S_ * D_ / 2,
        nullptr, 0, sth, stl, (long)M_ * D_ / 2,
        M_, D_, S_, nullptr);

    // 5. mem_out[b] = w_read[b] @ state[b]  -> fp32 for LN1
    bf_gemm<0, 0, 0><<<dim3(4, (S_ + 127) / 128, B_), 256, BF_SMEM_BYTES>>>(
        uh2, ul2, (long)S_ * M_ / 2,
        sth, stl, (long)M_ * D_ / 2,
        memout, (long)S_ * D_, nullptr, nullptr, 0,
        S_, D_, M_, nullptr);

    // 6. LN1 -> bf16
    layernorm16<<<R_, 128>>>(memout, hhh, hhl, ln1_g, ln1_b);

    // 7. attention projections -> fp32 for attention
    {
        PB3 p{aqh, aql, akh, akl, avh, avl,
              nullptr, nullptr, nullptr, nullptr, nullptr, nullptr};
        bf_gemm3<<<dim3(4, MT, 3), 256, BF_SMEM_BYTES>>>(
            hhh, hhl, p, R_, D_, D_, 0, qh, kh, vh);
    }

    // 8. banded flash attention -> bf16 aout
    attn_kernel<<<dim3((S_ + 63) / 64, H_, B_), 256,
                  ATTN_SMEM_FLOATS * (int)sizeof(float)>>>(qh, kh, vh, aoh, aol);

    // 9. Wo projection -> fp32 for LN2
    bf_gemm<0, 0, 0><<<dim3(4, MT, 1), 256, BF_SMEM_BYTES>>>(
        aoh, aol, 0, awh, awl, 0,
        ao2, 0, nullptr, nullptr, 0, R_, D_, D_, nullptr);

    // 10. LN2 -> bf16
    layernorm16<<<R_, 128>>>(ao2, g2h, g2l, ln2_g, ln2_b);

    // 11. final linear (+bias) -> fp32 output
    bf_gemm<0, 0, 0><<<dim3(4, MT, 1), 256, BF_SMEM_BYTES>>>(
        g2h, g2l, 0, owh, owl, 0,
        out, 0, nullptr, nullptr, 0, R_, D_, D_, out_b);
}

// round 12
// speedup vs baseline: 1.0862x; 1.0862x over previous
#include <cuda_runtime.h>
#include <cuda_bf16.h>

// ---------------- problem constants ----------------
#define B_   2
#define L_   2048
#define D_   512
#define P_   32
#define M_   1024
#define H_   8
#define HD_  64
#define WIN_ 256
#define S_   (P_ + L_)     // 2080
#define R_   (B_ * S_)     // 4160
#define EPS_ 1e-5f

// ---------------- scratch (device globals, no allocation) ----------------
__device__ float g_combined[R_ * D_];
__device__ float g_k[R_ * D_];
__device__ float g_v[R_ * D_];
__device__ float g_q[R_ * D_];
__device__ float g_w[R_ * M_];          // w_write
__device__ float g_w2[R_ * M_];         // w_read
__device__ float g_state[B_ * M_ * D_];
__device__ float g_memout[R_ * D_];
__device__ float g_h[R_ * D_];
__device__ float g_qh[R_ * D_];
__device__ float g_kh[R_ * D_];
__device__ float g_vh[R_ * D_];
__device__ float g_aout[R_ * D_];
__device__ float g_ao2[R_ * D_];
__device__ float g_h2[R_ * D_];

// ---------------- bf16 m16n8k16 MMA ----------------
#define MMA_BF16(d, a0, a1, a2, a3, b0, b1) \
    asm("mma.sync.aligned.m16n8k16.row.col.f32.bf16.bf16.f32 " \
        "{%0,%1,%2,%3}, {%4,%5,%6,%7}, {%8,%9}, {%0,%1,%2,%3};" \
        : "+f"((d)[0]), "+f"((d)[1]), "+f"((d)[2]), "+f"((d)[3]) \
        : "r"(a0), "r"(a1), "r"(a2), "r"(a3), "r"(b0), "r"(b1))

// hi/lo bf16 split of a float pair; packed words have LOW half = first elem.
__device__ __forceinline__ void hilo2(float x, float y, unsigned& h, unsigned& l) {
    __nv_bfloat162 hb = __floats2bfloat162_rn(x, y);
    float2 hf = __bfloat1622float2(hb);
    __nv_bfloat162 lb = __floats2bfloat162_rn(x - hf.x, y - hf.y);
    h = reinterpret_cast<unsigned&>(hb);
    l = reinterpret_cast<unsigned&>(lb);
}

// A-tile column permutation: (c, c+8) -> adjacent words (enables LDS.64).
// Bijective within each 16-column block.
__device__ __forceinline__ int sgm(int c) {
    return ((c & 7) << 1) + ((c >> 3) & 1) + (c & ~15);
}

// smem tile layout: [16 kpairs][136 cols] uints per matrix-half (R8 layout).
// A tiles store column sgm(c); B tiles store column c directly.
#define KPS  16
#define TSTR 136
#define MHALF (KPS * TSTR)                  // 2176 words
#define BUFW  (4 * MHALF)                   // Ahi|Alo|Bhi|Blo
#define BF_SMEM_BYTES (2 * BUFW * 4)        // 69632 B double buffered

// stage a row-major [rows, ld] fp32 source slab (32 k) into hi/lo tiles
template<int PERM>
__device__ __forceinline__ void stage_rm(
    const float* __restrict__ src, int r0, int RM, int ld, int k0,
    unsigned* __restrict__ Hi, unsigned* __restrict__ Lo, int tid) {
    const int row = tid >> 1;                 // tile col index 0..127
    const int kh  = (tid & 1) << 4;           // 0 or 16
    const int rw  = PERM ? sgm(row) : row;
    const float* p = src + (long)(r0 + row) * ld + k0 + kh;
    const bool ok = (r0 + row) < RM;
#pragma unroll
    for (int j = 0; j < 4; j++) {
        float4 a = ok ? *(const float4*)(p + j * 4)
                      : make_float4(0.f, 0.f, 0.f, 0.f);
        int kp = (kh >> 1) + 2 * j;
        unsigned h0, h1, l0, l1;
        hilo2(a.x, a.y, h0, l0);
        hilo2(a.z, a.w, h1, l1);
        Hi[kp * TSTR + rw] = h0; Hi[(kp + 1) * TSTR + rw] = h1;
        Lo[kp * TSTR + rw] = l0; Lo[(kp + 1) * TSTR + rw] = l1;
    }
}

// stage a [K, ld] fp32 source slab TRANSPOSED (tile cols = source columns)
template<int PERM>
__device__ __forceinline__ void stage_tr(
    const float* __restrict__ src, int c0, int CM, int ld, int k0,
    unsigned* __restrict__ Hi, unsigned* __restrict__ Lo, int tid) {
    const int kp = tid >> 4;                  // 0..15
    const int cq = (tid & 15) << 3;           // 0..120 step 8
    const bool ok = (c0 + cq) < CM;
    const float* p0 = src + (long)(k0 + 2 * kp) * ld + c0 + cq;
    const float* p1 = p0 + ld;
    float4 x0 = make_float4(0.f, 0.f, 0.f, 0.f), x1 = x0, y0 = x0, y1 = x0;
    if (ok) {
        x0 = *(const float4*)(p0);     x1 = *(const float4*)(p0 + 4);
        y0 = *(const float4*)(p1);     y1 = *(const float4*)(p1 + 4);
    }
    unsigned h[8], l[8];
    hilo2(x0.x, y0.x, h[0], l[0]); hilo2(x0.y, y0.y, h[1], l[1]);
    hilo2(x0.z, y0.z, h[2], l[2]); hilo2(x0.w, y0.w, h[3], l[3]);
    hilo2(x1.x, y1.x, h[4], l[4]); hilo2(x1.y, y1.y, h[5], l[5]);
    hilo2(x1.z, y1.z, h[6], l[6]); hilo2(x1.w, y1.w, h[7], l[7]);
    if (PERM) {
#pragma unroll
        for (int i2 = 0; i2 < 8; i2++) {
            int sl = sgm(cq + i2);
            Hi[kp * TSTR + sl] = h[i2];
            Lo[kp * TSTR + sl] = l[i2];
        }
    } else {
        *(uint4*)&Hi[kp * TSTR + cq]     = make_uint4(h[0], h[1], h[2], h[3]);
        *(uint4*)&Hi[kp * TSTR + cq + 4] = make_uint4(h[4], h[5], h[6], h[7]);
        *(uint4*)&Lo[kp * TSTR + cq]     = make_uint4(l[0], l[1], l[2], l[3]);
        *(uint4*)&Lo[kp * TSTR + cq + 4] = make_uint4(l[4], l[5], l[6], l[7]);
    }
}

// ---------------- bf16 2-split GEMM core: 128x128 tile, K-slab 32 --------
// C = A @ B (+bias).  ATR=0: A [M,K] row-major.  ATR=1: A stored [K,M].
// BTR=0: B stored [K,N].  BTR=1: B stored [N,K].
// Warp tile 64x32 (2x4 warp grid).  A-tile columns permuted (sgm) -> LDS.64.
template<int ATR, int BTR>
__device__ __forceinline__ void bf_core(
    const float* __restrict__ A, const float* __restrict__ Bm,
    float* __restrict__ C, int M, int N, int K, const float* __restrict__ bias) {
    extern __shared__ unsigned smg[];
    const int tid = threadIdx.x, lane = tid & 31, wid = tid >> 5;
    const int wm = (wid >> 2) * 64, wn = (wid & 3) * 32;
    const int m0 = blockIdx.y * 128, n0 = blockIdx.x * 128;

    float acc[4][4][4];
#pragma unroll
    for (int i = 0; i < 4; i++)
#pragma unroll
        for (int j = 0; j < 4; j++)
#pragma unroll
            for (int c = 0; c < 4; c++) acc[i][j][c] = 0.f;

    auto stage = [&](int s, int b) {
        const int k0 = s * 32;
        unsigned* AH = smg + b * BUFW;
        unsigned* AL = AH + MHALF;
        unsigned* BH = AH + 2 * MHALF;
        unsigned* BL = AH + 3 * MHALF;
        if (ATR == 0) stage_rm<1>(A, m0, M, K, k0, AH, AL, tid);
        else          stage_tr<1>(A, m0, M, M, k0, AH, AL, tid);
        if (BTR == 0) stage_tr<0>(Bm, n0, N, N, k0, BH, BL, tid);
        else          stage_rm<0>(Bm, n0, N, K, k0, BH, BL, tid);
    };

    const int slabs = K >> 5;
    stage(0, 0);
    __syncthreads();

    for (int s = 0; s < slabs; s++) {
        const int buf = s & 1;
        const unsigned* AH = smg + buf * BUFW;
        const unsigned* AL = AH + MHALF;
        const unsigned* BH = AH + 2 * MHALF;
        const unsigned* BL = AH + 3 * MHALF;
#pragma unroll
        for (int t = 0; t < 2; t++) {
            const int kb = (t * 8 + (lane & 3)) * TSTR;
            const int k4 = kb + 4 * TSTR;
            const int rsel = lane >> 2;
            unsigned bh0[4], bh1[4], bl0[4], bl1[4];
#pragma unroll
            for (int j = 0; j < 4; j++) {
                int c = wn + j * 8 + rsel;
                bh0[j] = BH[kb + c]; bh1[j] = BH[k4 + c];
                bl0[j] = BL[kb + c]; bl1[j] = BL[k4 + c];
            }
#pragma unroll
            for (int i = 0; i < 4; i++) {
                // sgm(c) with c = wm + i*16 + rsel (c&7 = rsel&7... wm,i*16
                // are multiples of 16, rsel<8) -> even slot 2*rsel; pair
                // (c, c+8) occupies slots (2*rsel, 2*rsel+1): one LDS.64.
                const int cp = wm + i * 16 + 2 * rsel;
                uint2 Hk0 = *(const uint2*)&AH[kb + cp];   // {a0, a1}
                uint2 Hk4 = *(const uint2*)&AH[k4 + cp];   // {a2, a3}
                uint2 Lk0 = *(const uint2*)&AL[kb + cp];
                uint2 Lk4 = *(const uint2*)&AL[k4 + cp];
#pragma unroll
                for (int j = 0; j < 4; j++) {
                    MMA_BF16(acc[i][j], Hk0.x, Hk0.y, Hk4.x, Hk4.y, bh0[j], bh1[j]);
                    MMA_BF16(acc[i][j], Hk0.x, Hk0.y, Hk4.x, Hk4.y, bl0[j], bl1[j]);
                    MMA_BF16(acc[i][j], Lk0.x, Lk0.y, Lk4.x, Lk4.y, bh0[j], bh1[j]);
                }
            }
        }
        if (s + 1 < slabs) stage(s + 1, buf ^ 1);
        __syncthreads();
    }

    // --- epilogue: c0,c1 -> row lane/4, cols 2*(lane%4); c2,c3 -> row+8 ---
    const int er = lane >> 2, ec = (lane & 3) * 2;
#pragma unroll
    for (int i = 0; i < 4; i++) {
#pragma unroll
        for (int j = 0; j < 4; j++) {
            int cc = n0 + wn + j * 8 + ec;
            float b0 = 0.f, b1 = 0.f;
            if (bias) { b0 = bias[cc]; b1 = bias[cc + 1]; }
            int r0w = m0 + wm + i * 16 + er;
            if (r0w < M)
                *(float2*)(C + (long)r0w * N + cc) =
                    make_float2(acc[i][j][0] + b0, acc[i][j][1] + b1);
            int r1w = r0w + 8;
            if (r1w < M)
                *(float2*)(C + (long)r1w * N + cc) =
                    make_float2(acc[i][j][2] + b0, acc[i][j][3] + b1);
        }
    }
}

template<int ATR, int BTR>
__global__ void __launch_bounds__(256, 2)
bf_gemm(const float* __restrict__ A, const float* __restrict__ Bm,
        float* __restrict__ C, int M, int N, int K,
        long sA, long sB, long sC, const float* __restrict__ bias) {
    bf_core<ATR, BTR>(A + blockIdx.z * sA, Bm + blockIdx.z * sB,
                      C + blockIdx.z * sC, M, N, K, bias);
}

struct Ptr3 { const float* b0; const float* b1; const float* b2;
              float* c0; float* c1; float* c2; };
__global__ void __launch_bounds__(256, 2)
bf_gemm3(const float* __restrict__ A, Ptr3 p, int M, int N, int K) {
    const float* Bm = (blockIdx.z == 0) ? p.b0 : (blockIdx.z == 1) ? p.b1 : p.b2;
    float*       C  = (blockIdx.z == 0) ? p.c0 : (blockIdx.z == 1) ? p.c1 : p.c2;
    bf_core<0, 0>(A, Bm, C, M, N, K, nullptr);
}

struct PtrW { const float* a0; const float* a1; float* c0; float* c1; };
__global__ void __launch_bounds__(256, 2)
bf_gemmW(PtrW p, const float* __restrict__ mk, int M, int N, int K) {
    bf_core<0, 1>(blockIdx.z ? p.a1 : p.a0, mk,
                  blockIdx.z ? p.c1 : p.c0, M, N, K, nullptr);
}

// ---------------- concat: combined = [persistent ; x] ----------------
__global__ void concat_kernel(const float* __restrict__ x,
                              const float* __restrict__ pm,
                              float* __restrict__ c) {
    long i = (long)blockIdx.x * 256 + threadIdx.x;
    if (i >= (long)R_ * D_) return;
    int d = (int)(i % D_);
    long sd = i / D_;
    int s = (int)(sd % S_);
    int b = (int)(sd / S_);
    c[i] = (s < P_) ? pm[s * D_ + d]
                    : x[((long)b * L_ + (s - P_)) * D_ + d];
}

// ---------------- row softmax over 1024 cols ----------------
__global__ void __launch_bounds__(256) softmax1024(float* __restrict__ w) {
    __shared__ float sh[8];
    float* row = w + (long)blockIdx.x * M_;
    const int tid = threadIdx.x;
    float4 v = *(float4*)(row + tid * 4);
    float mx = fmaxf(fmaxf(v.x, v.y), fmaxf(v.z, v.w));
#pragma unroll
    for (int o = 16; o; o >>= 1) mx = fmaxf(mx, __shfl_xor_sync(~0u, mx, o));
    if ((tid & 31) == 0) sh[tid >> 5] = mx;
    __syncthreads();
    mx = sh[0];
#pragma unroll
    for (int i = 1; i < 8; i++) mx = fmaxf(mx, sh[i]);
    v.x = __expf(v.x - mx); v.y = __expf(v.y - mx);
    v.z = __expf(v.z - mx); v.w = __expf(v.w - mx);
    float s = v.x + v.y + v.z + v.w;
#pragma unroll
    for (int o = 16; o; o >>= 1) s += __shfl_xor_sync(~0u, s, o);
    __syncthreads();
    if ((tid & 31) == 0) sh[tid >> 5] = s;
    __syncthreads();
    s = sh[0] + sh[1] + sh[2] + sh[3] + sh[4] + sh[5] + sh[6] + sh[7];
    float inv = 1.f / s;
    v.x *= inv; v.y *= inv; v.z *= inv; v.w *= inv;
    *(float4*)(row + tid * 4) = v;
}

// ---------------- layernorm, row width 512, 128 threads ----------------
__global__ void __launch_bounds__(128)
layernorm512(const float* __restrict__ in, float* __restrict__ out,
             const float* __restrict__ gw, const float* __restrict__ bw) {
    __shared__ float sh[4];
    const int tid = threadIdx.x;
    const float* row = in + (long)blockIdx.x * D_;
    float4 v = *(const float4*)(row + tid * 4);
    float s = v.x + v.y + v.z + v.w;
#pragma unroll
    for (int o = 16; o; o >>= 1) s += __shfl_xor_sync(~0u, s, o);
    if ((tid & 31) == 0) sh[tid >> 5] = s;
    __syncthreads();
    float mu = (sh[0] + sh[1] + sh[2] + sh[3]) * (1.f / 512.f);
    float dx = v.x - mu, dy = v.y - mu, dz = v.z - mu, dw = v.w - mu;
    float sq = dx * dx + dy * dy + dz * dz + dw * dw;
#pragma unroll
    for (int o = 16; o; o >>= 1) sq += __shfl_xor_sync(~0u, sq, o);
    __syncthreads();
    if ((tid & 31) == 0) sh[tid >> 5] = sq;
    __syncthreads();
    float var = (sh[0] + sh[1] + sh[2] + sh[3]) * (1.f / 512.f);
    float inv = rsqrtf(var + EPS_);
    float4 g4 = *(const float4*)(gw + tid * 4);
    float4 b4 = *(const float4*)(bw + tid * 4);
    float4 o;
    o.x = dx * inv * g4.x + b4.x;
    o.y = dy * inv * g4.y + b4.y;
    o.z = dz * inv * g4.z + b4.z;
    o.w = dw * inv * g4.w + b4.w;
    *(float4*)(out + (long)blockIdx.x * D_ + tid * 4) = o;
}

// ---------------- banded flash attention (R6 core, conflict-free smem) ----
#define QS_STR 68
#define PS_STR 69
#define ATTN_SMEM_FLOATS (64 * QS_STR + 64 * PS_STR + 64 * 64 * 2)
__global__ void __launch_bounds__(256)
attn_kernel(const float* __restrict__ qh, const float* __restrict__ kh,
            const float* __restrict__ vh, float* __restrict__ out) {
    extern __shared__ float smema[];
    float* Qs = smema;
    float* Ps = smema + 64 * QS_STR;
    float* Ks = Ps + 64 * PS_STR;
    float* Vs = Ks + 64 * 64;

    const int qt = blockIdx.x, h = blockIdx.y, b = blockIdx.z;
    const int q0 = qt * 64;
    const int tid = threadIdx.x;
    const int r = tid >> 2, cg = tid & 3;
    const int rowb = cg * 16;
    const long base = (long)b * S_ * D_ + h * HD_;

    for (int i = tid; i < 64 * 16; i += 256) {
        int rr = i >> 4, c4 = (i & 15) * 4;
        float4 qv = make_float4(0.f, 0.f, 0.f, 0.f);
        if (q0 + rr < S_)
            qv = *(const float4*)(qh + base + (long)(q0 + rr) * D_ + c4);
        *(float4*)&Qs[rr * QS_STR + c4] = qv;
    }

    float m = -1e30f, l = 0.f;
    float o[16];
#pragma unroll
    for (int i = 0; i < 16; i++) o[i] = 0.f;

    int klo = q0 - (WIN_ - 1); if (klo < 0) klo = 0;
    int khi = q0 + 63 + WIN_ - 1; if (khi > S_ - 1) khi = S_ - 1;

    for (int kt = klo >> 6; kt <= khi >> 6; ++kt) {
        const int k0 = kt << 6;
        __syncthreads();
        for (int i = tid; i < 64 * 16; i += 256) {
            int rr = i >> 4, c4 = (i & 15) * 4;
            float4 kv = make_float4(0.f, 0.f, 0.f, 0.f), vv = kv;
            if (k0 + rr < S_) {
                long g = base + (long)(k0 + rr) * D_ + c4;
                kv = *(const float4*)(kh + g);
                vv = *(const float4*)(vh + g);
            }
            *(float4*)&Ks[rr * 64 + (c4 ^ ((rr >> 4) * 8))] = kv;
            *(float4*)&Vs[rr * 64 + (c4 ^ ((c4 >> 5) * 8))] = vv;
        }
        __syncthreads();

        float sreg[16];
#pragma unroll
        for (int j = 0; j < 16; j++) sreg[j] = 0.f;
        const int kx = cg * 8;
#pragma unroll 4
        for (int d0 = 0; d0 < 64; d0 += 4) {
            float4 q4 = *(const float4*)&Qs[r * QS_STR + d0];
            const int kc = d0 ^ kx;
#pragma unroll
            for (int j = 0; j < 16; j++) {
                float4 k4 = *(const float4*)&Ks[(rowb + j) * 64 + kc];
                sreg[j] += q4.x * k4.x + q4.y * k4.y + q4.z * k4.z + q4.w * k4.w;
            }
        }

        const int qi = q0 + r;
        float tmax = -1e30f;
#pragma unroll
        for (int j = 0; j < 16; j++) {
            int kj = k0 + rowb + j;
            int diff = qi - kj; if (diff < 0) diff = -diff;
            bool valid = (kj < S_) && (diff < WIN_);
            sreg[j] = valid ? sreg[j] * 0.125f : -1e30f;
            tmax = fmaxf(tmax, sreg[j]);
        }
        tmax = fmaxf(tmax, __shfl_xor_sync(0xffffffffu, tmax, 1));
        tmax = fmaxf(tmax, __shfl_xor_sync(0xffffffffu, tmax, 2));
        float mnew = fmaxf(m, tmax);
        float alpha = __expf(m - mnew);
        float lsum = 0.f;
#pragma unroll
        for (int j = 0; j < 16; j++) {
            float p = (sreg[j] > -0.9e30f) ? __expf(sreg[j] - mnew) : 0.f;
            Ps[r * PS_STR + rowb + j] = p;
            lsum += p;
        }
        lsum += __shfl_xor_sync(0xffffffffu, lsum, 1);
        lsum += __shfl_xor_sync(0xffffffffu, lsum, 2);
        l = l * alpha + lsum;
        m = mnew;
#pragma unroll
        for (int i = 0; i < 16; i++) o[i] *= alpha;
        __syncthreads();

        const int vx = (cg >> 1) * 8;
#pragma unroll 4
        for (int j = 0; j < 64; j++) {
            float p = Ps[r * PS_STR + j];
#pragma unroll
            for (int i4 = 0; i4 < 4; i4++) {
                float4 v4 = *(const float4*)&Vs[j * 64 + ((rowb + i4 * 4) ^ vx)];
                o[i4 * 4 + 0] += p * v4.x;
                o[i4 * 4 + 1] += p * v4.y;
                o[i4 * 4 + 2] += p * v4.z;
                o[i4 * 4 + 3] += p * v4.w;
            }
        }
    }

    const int qi = q0 + r;
    if (qi < S_) {
        float inv = 1.f / l;
        float* orow = out + base + (long)qi * D_ + rowb;
#pragma unroll
        for (int i = 0; i < 16; i++) orow[i] = o[i] * inv;
    }
}

// ---------------- launch ----------------
extern "C" void kernel_launch(void* const* d_in, const int* in_sizes, int n_in,
                              void* d_out, int out_size) {
    const float* x        = (const float*)d_in[0];
    const float* pm       = (const float*)d_in[1];
    const float* mem_keys = (const float*)d_in[2];
    const float* mem_Wk   = (const float*)d_in[3];
    const float* mem_Wv   = (const float*)d_in[4];
    const float* mem_Wq   = (const float*)d_in[5];
    const float* attn_Wq  = (const float*)d_in[6];
    const float* attn_Wk  = (const float*)d_in[7];
    const float* attn_Wv  = (const float*)d_in[8];
    const float* attn_Wo  = (const float*)d_in[9];
    const float* ln1_g    = (const float*)d_in[10];
    const float* ln1_b    = (const float*)d_in[11];
    const float* ln2_g    = (const float*)d_in[12];
    const float* ln2_b    = (const float*)d_in[13];
    const float* out_W    = (const float*)d_in[14];
    const float* out_b    = (const float*)d_in[15];
    float* out = (float*)d_out;

    float *combined, *k, *v, *q, *w, *w2, *state, *memout, *h;
    float *qh, *kh, *vh, *aout, *ao2, *h2;
    cudaGetSymbolAddress((void**)&combined, g_combined);
    cudaGetSymbolAddress((void**)&k, g_k);
    cudaGetSymbolAddress((void**)&v, g_v);
    cudaGetSymbolAddress((void**)&q, g_q);
    cudaGetSymbolAddress((void**)&w, g_w);
    cudaGetSymbolAddress((void**)&w2, g_w2);
    cudaGetSymbolAddress((void**)&state, g_state);
    cudaGetSymbolAddress((void**)&memout, g_memout);
    cudaGetSymbolAddress((void**)&h, g_h);
    cudaGetSymbolAddress((void**)&qh, g_qh);
    cudaGetSymbolAddress((void**)&kh, g_kh);
    cudaGetSymbolAddress((void**)&vh, g_vh);
    cudaGetSymbolAddress((void**)&aout, g_aout);
    cudaGetSymbolAddress((void**)&ao2, g_ao2);
    cudaGetSymbolAddress((void**)&h2, g_h2);

    cudaFuncSetAttribute(attn_kernel,
                         cudaFuncAttributeMaxDynamicSharedMemorySize,
                         ATTN_SMEM_FLOATS * (int)sizeof(float));
    cudaFuncSetAttribute(bf_gemm3,
                         cudaFuncAttributeMaxDynamicSharedMemorySize, BF_SMEM_BYTES);
    cudaFuncSetAttribute(bf_gemmW,
                         cudaFuncAttributeMaxDynamicSharedMemorySize, BF_SMEM_BYTES);
    cudaFuncSetAttribute(bf_gemm<1, 0>,
                         cudaFuncAttributeMaxDynamicSharedMemorySize, BF_SMEM_BYTES);
    cudaFuncSetAttribute(bf_gemm<0, 0>,
                         cudaFuncAttributeMaxDynamicSharedMemorySize, BF_SMEM_BYTES);

    // 1. combined = [pm ; x]
    concat_kernel<<<(int)(((long)R_ * D_ + 255) / 256), 256>>>(x, pm, combined);

    const int MT = (R_ + 127) / 128;   // 33

    // 2. memory k/v/q projections
    {
        Ptr3 p{mem_Wk, mem_Wv, mem_Wq, k, v, q};
        bf_gemm3<<<dim3(4, MT, 3), 256, BF_SMEM_BYTES>>>(combined, p, R_, D_, D_);
    }

    // 3. gating: w_write = k@mkT, w_read = q@mkT  (mem_keys stored [N,K])
    {
        PtrW p{k, q, w, w2};
        bf_gemmW<<<dim3(8, MT, 2), 256, BF_SMEM_BYTES>>>(p, mem_keys, R_, M_, D_);
    }
    softmax1024<<<R_, 256>>>(w);
    softmax1024<<<R_, 256>>>(w2);

    // 4. state[b] = w_write[b]^T @ v[b]   (A stored [K=S, M=1024])
    bf_gemm<1, 0><<<dim3(4, 8, B_), 256, BF_SMEM_BYTES>>>(
        w, v, state, M_, D_, S_,
        (long)S_ * M_, (long)S_ * D_, (long)M_ * D_, nullptr);

    // 5. mem_out[b] = w_read[b] @ state[b]
    bf_gemm<0, 0><<<dim3(4, (S_ + 127) / 128, B_), 256, BF_SMEM_BYTES>>>(
        w2, state, memout, S_, D_, M_,
        (long)S_ * M_, (long)M_ * D_, (long)S_ * D_, nullptr);

    // 6. LN1
    layernorm512<<<R_, 128>>>(memout, h, ln1_g, ln1_b);

    // 7. attention projections
    {
        Ptr3 p{attn_Wq, attn_Wk, attn_Wv, qh, kh, vh};
        bf_gemm3<<<dim3(4, MT, 3), 256, BF_SMEM_BYTES>>>(h, p, R_, D_, D_);
    }

    // 8. banded flash attention
    attn_kernel<<<dim3((S_ + 63) / 64, H_, B_), 256,
                  ATTN_SMEM_FLOATS * (int)sizeof(float)>>>(qh, kh, vh, aout);

    // 9. output projection + LN2 + final linear (+bias)
    bf_gemm<0, 0><<<dim3(4, MT, 1), 256, BF_SMEM_BYTES>>>(
        aout, attn_Wo, ao2, R_, D_, D_, 0, 0, 0, nullptr);
    layernorm512<<<R_, 128>>>(ao2, h2, ln2_g, ln2_b);
    bf_gemm<0, 0><<<dim3(4, MT, 1), 256, BF_SMEM_BYTES>>>(
        h2, out_W, out, R_, D_, D_, 0, 0, 0, out_b);
}